// round 1
// baseline (speedup 1.0000x reference)
#include <cuda_runtime.h>

#define BB   8
#define CIN  8
#define COUT 16
#define HH   256
#define WW   256
#define HW   (HH * WW)          // 65536
#define NPIX (BB * HW)          // 524288
#define GROUPS_PER_IMG (HW / 4) // 16384 pixel-groups (float4) per batch image

__device__ __forceinline__ float ex2(float v) {
    float r;
    asm("ex2.approx.ftz.f32 %0, %1;" : "=f"(r) : "f"(v));
    return r;
}

__global__ __launch_bounds__(256) void rbf_hist_kernel(
    const float* __restrict__ x,
    const float* __restrict__ centers,
    const float* __restrict__ widths,
    float* __restrict__ out)
{
    __shared__ float s_c[COUT * CIN];
    __shared__ float s_k[COUT * CIN];

    int tid = threadIdx.x;
    if (tid < COUT * CIN) {
        s_c[tid] = centers[tid];
        float w = widths[tid];
        // exp(-d^2/(2w^2)) = exp2(d^2 * k),  k = -log2(e)/(2w^2)
        s_k[tid] = -1.44269504088896340736f / (2.0f * w * w);
    }
    __syncthreads();

    int idx = blockIdx.x * blockDim.x + tid;    // pixel-group id, 0..131071
    int b   = idx >> 14;                         // / GROUPS_PER_IMG
    int p4  = idx & (GROUPS_PER_IMG - 1);        // group within image
    int xbase = b * CIN * HW + p4 * 4;
    int obase = b * COUT * HW + p4 * 4;

    // Load the 8 input channels for these 4 pixels once; reuse for all 16 outputs.
    float4 xv[CIN];
    #pragma unroll
    for (int j = 0; j < CIN; j++)
        xv[j] = *reinterpret_cast<const float4*>(x + xbase + j * HW);

    #pragma unroll 4
    for (int o = 0; o < COUT; o++) {
        float a0 = 0.f, a1 = 0.f, a2 = 0.f, a3 = 0.f;
        #pragma unroll
        for (int j = 0; j < CIN; j++) {
            float c = s_c[o * CIN + j];
            float k = s_k[o * CIN + j];
            float d0 = xv[j].x - c;
            float d1 = xv[j].y - c;
            float d2 = xv[j].z - c;
            float d3 = xv[j].w - c;
            a0 += ex2(d0 * k * d0);
            a1 += ex2(d1 * k * d1);
            a2 += ex2(d2 * k * d2);
            a3 += ex2(d3 * k * d3);
        }
        float4 r = make_float4(a0, a1, a2, a3);
        *reinterpret_cast<float4*>(out + obase + o * HW) = r;
    }
}

extern "C" void kernel_launch(void* const* d_in, const int* in_sizes, int n_in,
                              void* d_out, int out_size)
{
    const float* x       = (const float*)d_in[0];
    const float* centers = (const float*)d_in[1];
    const float* widths  = (const float*)d_in[2];
    float* out           = (float*)d_out;

    const int threads = 256;
    const int groups  = NPIX / 4;                 // 131072 threads total
    const int blocks  = groups / threads;         // 512 blocks
    rbf_hist_kernel<<<blocks, threads>>>(x, centers, widths, out);
}

// round 2
// speedup vs baseline: 1.1556x; 1.1556x over previous
#include <cuda_runtime.h>
#include <cstring>

#define BB   8
#define CIN  8
#define COUT 16
#define HH   256
#define WW   256
#define HW   (HH * WW)          // 65536
#define NPIX (BB * HW)          // 524288
#define GROUPS_PER_IMG (HW / 4) // 16384 float4 pixel-groups per image

__device__ __forceinline__ float ex2(float v) {
    float r;
    asm("ex2.approx.ftz.f32 %0, %1;" : "=f"(r) : "f"(v));
    return r;
}

// Packed f32x2 ops (Blackwell sm_103a): one instruction operates on two floats.
__device__ __forceinline__ float2 add2(float2 a, float2 b) {
    unsigned long long ra, rb, rr;
    memcpy(&ra, &a, 8); memcpy(&rb, &b, 8);
    asm("add.rn.f32x2 %0, %1, %2;" : "=l"(rr) : "l"(ra), "l"(rb));
    float2 r; memcpy(&r, &rr, 8);
    return r;
}
__device__ __forceinline__ float2 mul2(float2 a, float2 b) {
    unsigned long long ra, rb, rr;
    memcpy(&ra, &a, 8); memcpy(&rb, &b, 8);
    asm("mul.rn.f32x2 %0, %1, %2;" : "=l"(rr) : "l"(ra), "l"(rb));
    float2 r; memcpy(&r, &rr, 8);
    return r;
}

__global__ __launch_bounds__(128) void rbf_hist_kernel(
    const float* __restrict__ x,
    const float* __restrict__ centers,
    const float* __restrict__ widths,
    float* __restrict__ out)
{
    // Packed (broadcast) coefficients: nc = (-c,-c), k = (k,k)
    __shared__ float2 s_nc[COUT * CIN];
    __shared__ float2 s_k[COUT * CIN];

    int tid = threadIdx.x;
    if (tid < COUT * CIN) {
        float c = centers[tid];
        float w = widths[tid];
        float k = -1.44269504088896340736f / (2.0f * w * w); // exp(-d^2/2w^2)=exp2(k d^2)
        s_nc[tid] = make_float2(-c, -c);
        s_k[tid]  = make_float2(k, k);
    }
    __syncthreads();

    int idx = blockIdx.x * blockDim.x + tid;    // pixel-group id, 0..131071
    int b   = idx >> 14;                         // / GROUPS_PER_IMG
    int p4  = idx & (GROUPS_PER_IMG - 1);
    int xbase = b * CIN * HW + p4 * 4;
    int obase = b * COUT * HW + p4 * 4;

    // Load 8 channels x 4 pixels once, as two packed pairs per channel.
    float2 xa[CIN], xb[CIN];
    #pragma unroll
    for (int j = 0; j < CIN; j++) {
        float4 v = *reinterpret_cast<const float4*>(x + xbase + j * HW);
        xa[j] = make_float2(v.x, v.y);
        xb[j] = make_float2(v.z, v.w);
    }

    #pragma unroll 4
    for (int o = 0; o < COUT; o++) {
        float2 accA = make_float2(0.f, 0.f);
        float2 accB = make_float2(0.f, 0.f);
        #pragma unroll
        for (int j = 0; j < CIN; j++) {
            float2 nc = s_nc[o * CIN + j];
            float2 k  = s_k[o * CIN + j];
            float2 dA = add2(xa[j], nc);
            float2 dB = add2(xb[j], nc);
            float2 tA = mul2(dA, k);
            float2 tB = mul2(dB, k);
            float2 gA = mul2(tA, dA);
            float2 gB = mul2(tB, dB);
            accA = add2(accA, make_float2(ex2(gA.x), ex2(gA.y)));
            accB = add2(accB, make_float2(ex2(gB.x), ex2(gB.y)));
        }
        float4 r = make_float4(accA.x, accA.y, accB.x, accB.y);
        *reinterpret_cast<float4*>(out + obase + o * HW) = r;
    }
}

extern "C" void kernel_launch(void* const* d_in, const int* in_sizes, int n_in,
                              void* d_out, int out_size)
{
    const float* x       = (const float*)d_in[0];
    const float* centers = (const float*)d_in[1];
    const float* widths  = (const float*)d_in[2];
    float* out           = (float*)d_out;

    const int threads = 128;
    const int groups  = NPIX / 4;                 // 131072 threads
    const int blocks  = groups / threads;         // 1024 blocks
    rbf_hist_kernel<<<blocks, threads>>>(x, centers, widths, out);
}